// round 5
// baseline (speedup 1.0000x reference)
#include <cuda_runtime.h>

#define BN 8
#define NP 2000
#define NG 100
#define MH 320
#define MW 320
#define NUM_POS 66
#define NUM_NEG 134
#define TRAIN_ROIS 200
#define MASK_H 28
#define MASK_W 28

// output layout (flattened tuple, float32)
#define ROIS_OFF  0
#define CLS_OFF   (BN*TRAIN_ROIS*4)            /* 6400 */
#define DELTA_OFF (CLS_OFF + BN*TRAIN_ROIS)    /* 8000 */
#define MASK_OFF  (DELTA_OFF + BN*TRAIN_ROIS*4)/* 14400 */

__device__ float g_maxiou[BN*NP];
__device__ int   g_arg[BN*NP];
__device__ int   g_valid[BN*NP];
__device__ int   g_poslist[BN*NUM_POS];
__device__ int   g_neglist[BN*NUM_NEG];
__device__ int   g_poscount[BN];
__device__ int   g_negcount[BN];

// XLA GPU compiles f32 divide with nvptx-prec-divf32=1 -> div.full.f32.
// Emit the identical instruction so every division is bit-identical.
__device__ __forceinline__ float xdiv(float a, float b) {
    float r;
    asm("div.full.f32 %0, %1, %2;" : "=f"(r) : "f"(a), "f"(b));
    return r;
}

// ---------------------------------------------------------------------------
// Kernel 1: per-proposal max IoU + argmax (first-max tie break = jnp.argmax)
// Explicit round-to-nearest mul/add (no FMA contraction) + div.full division:
// bit-identical to XLA's elementwise HLOs.
// ---------------------------------------------------------------------------
__global__ void iou_kernel(const float4* __restrict__ props,
                           const float4* __restrict__ gts)
{
    int idx = blockIdx.x * blockDim.x + threadIdx.x;
    if (idx >= BN*NP) return;
    int b = idx / NP;
    float4 p = props[idx];
    int valid = (p.x!=0.f)||(p.y!=0.f)||(p.z!=0.f)||(p.w!=0.f);
    float area_a = __fmul_rn(__fsub_rn(p.z,p.x), __fsub_rn(p.w,p.y));
    float best = -2.0f; int bg = 0;
    #pragma unroll 4
    for (int g = 0; g < NG; ++g) {
        float4 q = gts[b*NG + g];
        int vg = (q.x!=0.f)||(q.y!=0.f)||(q.z!=0.f)||(q.w!=0.f);
        float y1 = fmaxf(p.x, q.x), x1 = fmaxf(p.y, q.y);
        float y2 = fminf(p.z, q.z), x2 = fminf(p.w, q.w);
        float inter = __fmul_rn(fmaxf(__fsub_rn(y2,y1),0.f),
                                fmaxf(__fsub_rn(x2,x1),0.f));
        float area_b = __fmul_rn(__fsub_rn(q.z,q.x), __fsub_rn(q.w,q.y));
        float uni = __fsub_rn(__fadd_rn(area_a, area_b), inter);
        float iou = xdiv(inter, fmaxf(uni, 1e-8f));
        float v = (vg && valid) ? iou : -1.0f;
        if (v > best) { best = v; bg = g; }
    }
    g_maxiou[idx] = best;
    g_arg[idx]    = bg;
    g_valid[idx]  = valid;
}

// ---------------------------------------------------------------------------
// Kernel 2: literal lax.top_k via iterative argmax over packed 64-bit keys.
// key = orderable(v) << 32 | (NP-1-i): max picks highest value; ties pick the
// LOWEST index — exactly lax.top_k's tie-break. Winners cleared, re-selected.
// ---------------------------------------------------------------------------
__device__ __forceinline__ unsigned long long umax64(unsigned long long a,
                                                     unsigned long long b) {
    return a > b ? a : b;
}
__device__ __forceinline__ unsigned orderable(float v) {
    unsigned u = __float_as_uint(v);
    return (u & 0x80000000u) ? ~u : (u | 0x80000000u);
}

__global__ __launch_bounds__(1024) void select_kernel()
{
    int b = blockIdx.x, t = threadIdx.x;
    __shared__ unsigned long long vals[2048];
    __shared__ unsigned long long red[1024];
    __shared__ int sh_cnt;

    // ---------------- positives: v >= 0.5 ----------------
    if (t == 0) sh_cnt = 0;
    __syncthreads();
    int local = 0;
    for (int i = t; i < 2048; i += 1024) {
        unsigned long long k = 0ull;
        if (i < NP) {
            float v = g_maxiou[b*NP + i];
            if (v >= 0.5f) {
                k = (((unsigned long long)orderable(v)) << 32)
                  | (unsigned)(NP - 1 - i);
                local++;
            }
        }
        vals[i] = k;
    }
    atomicAdd(&sh_cnt, local);
    __syncthreads();
    int pc = min(sh_cnt, NUM_POS);

    for (int s = 0; s < pc; ++s) {
        red[t] = umax64(vals[t], vals[t + 1024]);
        __syncthreads();
        #pragma unroll
        for (int off = 512; off > 0; off >>= 1) {
            if (t < off) red[t] = umax64(red[t], red[t + off]);
            __syncthreads();
        }
        if (t == 0) {
            int wi = NP - 1 - (int)(red[0] & 0xFFFFFFFFu);
            g_poslist[b*NUM_POS + s] = wi;
            vals[wi] = 0ull;
        }
        __syncthreads();
    }

    // ---------------- negatives: v < 0.5 && valid ----------------
    if (t == 0) sh_cnt = 0;
    __syncthreads();
    local = 0;
    for (int i = t; i < 2048; i += 1024) {
        unsigned long long k = 0ull;
        if (i < NP) {
            float v = g_maxiou[b*NP + i];
            if ((v < 0.5f) && g_valid[b*NP + i]) {
                k = (((unsigned long long)orderable(v)) << 32)
                  | (unsigned)(NP - 1 - i);
                local++;
            }
        }
        vals[i] = k;
    }
    atomicAdd(&sh_cnt, local);
    __syncthreads();
    int tn = sh_cnt;

    // neg_count = int32(float32(pc) / 0.33f) - pc, clamped; division is
    // the reference's actual div.full instruction (66/0.33f -> 200.0).
    int nc = (int)xdiv((float)pc, 0.33f) - pc;
    nc = min(nc, tn);
    nc = min(nc, NUM_NEG);
    if (nc < 0) nc = 0;

    for (int s = 0; s < nc; ++s) {
        red[t] = umax64(vals[t], vals[t + 1024]);
        __syncthreads();
        #pragma unroll
        for (int off = 512; off > 0; off >>= 1) {
            if (t < off) red[t] = umax64(red[t], red[t + off]);
            __syncthreads();
        }
        if (t == 0) {
            int wi = NP - 1 - (int)(red[0] & 0xFFFFFFFFu);
            g_neglist[b*NUM_NEG + s] = wi;
            vals[wi] = 0ull;
        }
        __syncthreads();
    }

    if (t == 0) {
        g_poscount[b] = pc;
        g_negcount[b] = nc;
    }
}

// ---------------------------------------------------------------------------
// Kernel 3: zero-fill output
// ---------------------------------------------------------------------------
__global__ void zero_kernel(float* __restrict__ out, int n)
{
    for (int i = blockIdx.x*blockDim.x + threadIdx.x; i < n; i += gridDim.x*blockDim.x)
        out[i] = 0.0f;
}

// ---------------------------------------------------------------------------
// Kernel 4: rois, class ids, deltas for selected slots
// ---------------------------------------------------------------------------
__global__ void slots_kernel(const float4* __restrict__ props,
                             const float4* __restrict__ gts,
                             const int*    __restrict__ cls,
                             float* __restrict__ out)
{
    int b = blockIdx.x;
    int t = threadIdx.x;
    if (t >= TRAIN_ROIS) return;
    int pc = g_poscount[b], nc = g_negcount[b];

    if (t < NUM_POS) {
        if (t < pc) {
            int p = g_poslist[b*NUM_POS + t];
            float4 r = props[b*NP + p];
            float* ro = out + ROIS_OFF + (size_t)(b*TRAIN_ROIS + t)*4;
            ro[0]=r.x; ro[1]=r.y; ro[2]=r.z; ro[3]=r.w;

            int g = g_arg[b*NP + p];
            out[CLS_OFF + b*TRAIN_ROIS + t] = (float)cls[b*NG + g];

            float4 q = gts[b*NG + g];
            float h  = fmaxf(__fsub_rn(r.z,r.x), 1e-8f);
            float w  = fmaxf(__fsub_rn(r.w,r.y), 1e-8f);
            float cy = __fadd_rn(r.x, __fmul_rn(0.5f,h));
            float cx = __fadd_rn(r.y, __fmul_rn(0.5f,w));
            float gh  = fmaxf(__fsub_rn(q.z,q.x), 1e-8f);
            float gw  = fmaxf(__fsub_rn(q.w,q.y), 1e-8f);
            float gcy = __fadd_rn(q.x, __fmul_rn(0.5f,gh));
            float gcx = __fadd_rn(q.y, __fmul_rn(0.5f,gw));
            float* dd = out + DELTA_OFF + (size_t)(b*TRAIN_ROIS + t)*4;
            dd[0] = xdiv(xdiv(__fsub_rn(gcy,cy), h), 0.1f);
            dd[1] = xdiv(xdiv(__fsub_rn(gcx,cx), w), 0.1f);
            dd[2] = xdiv(logf(xdiv(gh,h)), 0.2f);
            dd[3] = xdiv(logf(xdiv(gw,w)), 0.2f);
        }
    } else {
        int j = t - NUM_POS;
        if (j < nc) {
            int p = g_neglist[b*NUM_NEG + j];
            float4 r = props[b*NP + p];
            float* ro = out + ROIS_OFF + (size_t)(b*TRAIN_ROIS + t)*4;
            ro[0]=r.x; ro[1]=r.y; ro[2]=r.z; ro[3]=r.w;
        }
    }
}

// ---------------------------------------------------------------------------
// Kernel 5: bilinear 28x28 mask crops for positive slots.
// fy/fx use the reference's div.full instruction so floor/round decisions
// are bit-identical.
// ---------------------------------------------------------------------------
__global__ void mask_kernel(const float4* __restrict__ props,
                            const unsigned int* __restrict__ masks,
                            float* __restrict__ out)
{
    int b = blockIdx.y, i = blockIdx.x;
    if (i >= g_poscount[b]) return;
    int p = g_poslist[b*NUM_POS + i];
    float4 r = props[b*NP + p];
    int g = g_arg[b*NP + p];

    int t = threadIdx.x;                  // 0..783
    int y = t / MASK_W, x = t % MASK_W;

    float fy = xdiv((float)y, (float)(MASK_H-1));
    float fx = xdiv((float)x, (float)(MASK_W-1));
    float sy = __fadd_rn(__fmul_rn(r.x, 319.f),
                         __fmul_rn(__fmul_rn(fy, __fsub_rn(r.z,r.x)), 319.f));
    sy = fminf(fmaxf(sy, 0.f), 319.f);
    float sx = __fadd_rn(__fmul_rn(r.y, 319.f),
                         __fmul_rn(__fmul_rn(fx, __fsub_rn(r.w,r.y)), 319.f));
    sx = fminf(fmaxf(sx, 0.f), 319.f);

    int y0 = min(max((int)floorf(sy), 0), MH-2);
    int x0 = min(max((int)floorf(sx), 0), MW-2);
    float wy = __fsub_rn(sy, (float)y0);
    float wx = __fsub_rn(sx, (float)x0);

    size_t i00 = (((size_t)b*MH + y0)*MW + x0)*NG + g;
    float c00 = masks[i00]                    ? 1.f : 0.f;
    float c01 = masks[i00 + NG]               ? 1.f : 0.f;
    float c10 = masks[i00 + (size_t)MW*NG]    ? 1.f : 0.f;
    float c11 = masks[i00 + (size_t)MW*NG+NG] ? 1.f : 0.f;

    float top = __fadd_rn(__fmul_rn(c00, __fsub_rn(1.f,wx)), __fmul_rn(c01, wx));
    float bot = __fadd_rn(__fmul_rn(c10, __fsub_rn(1.f,wx)), __fmul_rn(c11, wx));
    float val = __fadd_rn(__fmul_rn(top, __fsub_rn(1.f,wy)), __fmul_rn(bot, wy));

    out[MASK_OFF + ((size_t)(b*TRAIN_ROIS) + i)*(MASK_H*MASK_W) + t] = rintf(val);
}

// ---------------------------------------------------------------------------
extern "C" void kernel_launch(void* const* d_in, const int* in_sizes, int n_in,
                              void* d_out, int out_size)
{
    // Bind inputs by element count (all four are distinct) — immune to ordering.
    const float4*       props = 0;
    const int*          cls   = 0;
    const float4*       gts   = 0;
    const unsigned int* masks = 0;
    for (int i = 0; i < n_in; ++i) {
        switch (in_sizes[i]) {
            case BN*NP*4:              props = (const float4*)d_in[i];       break;
            case BN*NG:                cls   = (const int*)d_in[i];          break;
            case BN*NG*4:              gts   = (const float4*)d_in[i];       break;
            default:                   masks = (const unsigned int*)d_in[i]; break;
        }
    }
    float* out = (float*)d_out;

    iou_kernel<<<(BN*NP + 255)/256, 256>>>(props, gts);
    select_kernel<<<BN, 1024>>>();
    zero_kernel<<<512, 256>>>(out, out_size);
    slots_kernel<<<BN, 256>>>(props, gts, cls, out);
    mask_kernel<<<dim3(NUM_POS, BN), MASK_H*MASK_W>>>(props, masks, out);
}

// round 6
// speedup vs baseline: 2.8401x; 2.8401x over previous
#include <cuda_runtime.h>

#define BN 8
#define NP 2000
#define NG 100
#define MH 320
#define MW 320
#define NUM_POS 66
#define NUM_NEG 134
#define TRAIN_ROIS 200
#define MASK_H 28
#define MASK_W 28

// output layout (flattened tuple, float32)
#define ROIS_OFF  0
#define CLS_OFF   (BN*TRAIN_ROIS*4)            /* 6400 */
#define DELTA_OFF (CLS_OFF + BN*TRAIN_ROIS)    /* 8000 */
#define MASK_OFF  (DELTA_OFF + BN*TRAIN_ROIS*4)/* 14400 */

__device__ int g_arg[BN*NP];
__device__ int g_poslist[BN*NUM_POS];
__device__ int g_neglist[BN*NUM_NEG];
__device__ int g_poscount[BN];
__device__ int g_negcount[BN];

// XLA GPU compiles f32 divide with nvptx-prec-divf32=1 -> div.full.f32.
// Emit the identical instruction so every division is bit-identical.
__device__ __forceinline__ float xdiv(float a, float b) {
    float r;
    asm("div.full.f32 %0, %1, %2;" : "=f"(r) : "f"(a), "f"(b));
    return r;
}

__device__ __forceinline__ unsigned orderable(float v) {
    unsigned u = __float_as_uint(v);
    return (u & 0x80000000u) ? ~u : (u | 0x80000000u);
}
// pos test on packed key hi word: v >= 0.5 <=> hi = ~ord(v) <= ~ord(0.5)
__device__ __forceinline__ int pos_hi(unsigned hi) { return hi <= 0x40FFFFFFu; }

// ---------------------------------------------------------------------------
// Kernel A (one block of 1024 per batch): fused IoU + selection.
//  1) IoU max/argmax for 2000 proposals vs 100 GTs (GTs staged in shared).
//  2) One bitonic sort of 2048 keys (~ord(v))<<32 | idx  => (value desc, idx asc):
//     filtering this single sorted order by the pos/neg predicates reproduces
//     both lax.top_k selections exactly (continuous values; tie=lowest index).
//  3) Two filtered Hillis-Steele scans extract pos/neg lists + counts.
// ---------------------------------------------------------------------------
__global__ __launch_bounds__(1024) void fused_select(const float4* __restrict__ props,
                                                     const float4* __restrict__ gts)
{
    int b = blockIdx.x, t = threadIdx.x;
    __shared__ float4 sg[NG];
    __shared__ unsigned char svg[NG];
    __shared__ unsigned long long keys[2048];
    __shared__ unsigned char svalid[2048];
    __shared__ int scanbuf[1024];
    __shared__ int totals[2];

    if (t < NG) {
        float4 q = gts[b*NG + t];
        sg[t] = q;
        svg[t] = (q.x!=0.f)||(q.y!=0.f)||(q.z!=0.f)||(q.w!=0.f);
    }
    __syncthreads();

    // ---- IoU + argmax (first-max tie break = jnp.argmax) ----
    for (int i = t; i < 2048; i += 1024) {
        unsigned long long k = ~0ull;      // padding sorts to the end
        unsigned char valid = 0;
        if (i < NP) {
            float4 p = props[b*NP + i];
            valid = (p.x!=0.f)||(p.y!=0.f)||(p.z!=0.f)||(p.w!=0.f);
            float area_a = __fmul_rn(__fsub_rn(p.z,p.x), __fsub_rn(p.w,p.y));
            float best = -2.0f; int bg = 0;
            #pragma unroll 4
            for (int g = 0; g < NG; ++g) {
                float4 q = sg[g];
                float y1 = fmaxf(p.x, q.x), x1 = fmaxf(p.y, q.y);
                float y2 = fminf(p.z, q.z), x2 = fminf(p.w, q.w);
                float inter = __fmul_rn(fmaxf(__fsub_rn(y2,y1),0.f),
                                        fmaxf(__fsub_rn(x2,x1),0.f));
                float area_b = __fmul_rn(__fsub_rn(q.z,q.x), __fsub_rn(q.w,q.y));
                float uni = __fsub_rn(__fadd_rn(area_a, area_b), inter);
                float iou = xdiv(inter, fmaxf(uni, 1e-8f));
                float v = (svg[g] && valid) ? iou : -1.0f;
                if (v > best) { best = v; bg = g; }
            }
            g_arg[b*NP + i] = bg;
            k = (((unsigned long long)(~orderable(best))) << 32) | (unsigned)i;
        }
        keys[i] = k;
        svalid[i] = valid;
    }
    __syncthreads();

    // ---- bitonic sort ascending: (value desc, idx asc) ----
    for (int kk = 2; kk <= 2048; kk <<= 1) {
        for (int j = kk >> 1; j > 0; j >>= 1) {
            #pragma unroll
            for (int rep = 0; rep < 2; ++rep) {
                int i = t + rep*1024;
                int ix = i ^ j;
                if (ix > i) {
                    bool up = ((i & kk) == 0);
                    unsigned long long a = keys[i], c = keys[ix];
                    if ((a > c) == up) { keys[i] = c; keys[ix] = a; }
                }
            }
            __syncthreads();
        }
    }

    // ---- filtered extraction (pass 0: pos, pass 1: neg) ----
    for (int pass = 0; pass < 2; ++pass) {
        unsigned long long k0 = keys[2*t], k1 = keys[2*t+1];
        unsigned hi0 = (unsigned)(k0 >> 32), hi1 = (unsigned)(k1 >> 32);
        unsigned id0 = (unsigned)(k0 & 0xFFFFFFFFu), id1 = (unsigned)(k1 & 0xFFFFFFFFu);
        int fa, fb;
        if (pass == 0) {
            fa = pos_hi(hi0);
            fb = pos_hi(hi1);
        } else {
            fa = (id0 < NP) && !pos_hi(hi0) && svalid[id0];
            fb = (id1 < NP) && !pos_hi(hi1) && svalid[id1];
        }
        int s = fa + fb;
        scanbuf[t] = s;
        __syncthreads();
        for (int off = 1; off < 1024; off <<= 1) {
            int v = scanbuf[t];
            if (t >= off) v += scanbuf[t - off];
            __syncthreads();
            scanbuf[t] = v;
            __syncthreads();
        }
        int incl = scanbuf[t];
        int excl = incl - s;
        int lim  = (pass == 0) ? NUM_POS : NUM_NEG;
        int* list = (pass == 0) ? (g_poslist + b*NUM_POS) : (g_neglist + b*NUM_NEG);
        if (fa && excl < lim)        list[excl]      = (int)id0;
        if (fb && (excl + fa) < lim) list[excl + fa] = (int)id1;
        if (t == 1023) totals[pass] = incl;
        __syncthreads();
    }

    if (t == 0) {
        int pc = min(totals[0], NUM_POS);
        // neg_count = int32(f32(pc)/0.33f) - pc with the reference's div.full
        int nc = (int)xdiv((float)pc, 0.33f) - pc;
        nc = min(nc, totals[1]);
        nc = min(nc, NUM_NEG);
        if (nc < 0) nc = 0;
        g_poscount[b] = pc;
        g_negcount[b] = nc;
    }
}

// ---------------------------------------------------------------------------
// Kernel B: rois, class ids, deltas for ALL 200 slots (zeros when unselected)
// ---------------------------------------------------------------------------
__global__ void slots_kernel(const float4* __restrict__ props,
                             const float4* __restrict__ gts,
                             const int*    __restrict__ cls,
                             float* __restrict__ out)
{
    int b = blockIdx.x;
    int t = threadIdx.x;
    if (t >= TRAIN_ROIS) return;
    int pc = g_poscount[b], nc = g_negcount[b];

    float4 roi = make_float4(0.f,0.f,0.f,0.f);
    float  c   = 0.f;
    float4 dd  = make_float4(0.f,0.f,0.f,0.f);

    if (t < NUM_POS) {
        if (t < pc) {
            int p = g_poslist[b*NUM_POS + t];
            float4 r = props[b*NP + p];
            roi = r;
            int g = g_arg[b*NP + p];
            c = (float)cls[b*NG + g];
            float4 q = gts[b*NG + g];
            float h  = fmaxf(__fsub_rn(r.z,r.x), 1e-8f);
            float w  = fmaxf(__fsub_rn(r.w,r.y), 1e-8f);
            float cy = __fadd_rn(r.x, __fmul_rn(0.5f,h));
            float cx = __fadd_rn(r.y, __fmul_rn(0.5f,w));
            float gh  = fmaxf(__fsub_rn(q.z,q.x), 1e-8f);
            float gw  = fmaxf(__fsub_rn(q.w,q.y), 1e-8f);
            float gcy = __fadd_rn(q.x, __fmul_rn(0.5f,gh));
            float gcx = __fadd_rn(q.y, __fmul_rn(0.5f,gw));
            dd.x = xdiv(xdiv(__fsub_rn(gcy,cy), h), 0.1f);
            dd.y = xdiv(xdiv(__fsub_rn(gcx,cx), w), 0.1f);
            dd.z = xdiv(logf(xdiv(gh,h)), 0.2f);
            dd.w = xdiv(logf(xdiv(gw,w)), 0.2f);
        }
    } else {
        int j = t - NUM_POS;
        if (j < nc) {
            int p = g_neglist[b*NUM_NEG + j];
            roi = props[b*NP + p];
        }
    }

    ((float4*)(out + ROIS_OFF))[b*TRAIN_ROIS + t]  = roi;
    out[CLS_OFF + b*TRAIN_ROIS + t]                = c;
    ((float4*)(out + DELTA_OFF))[b*TRAIN_ROIS + t] = dd;
}

// ---------------------------------------------------------------------------
// Kernel C: masks for ALL 200 slots per batch (bilinear crop for selected
// positives, zeros elsewhere).
// ---------------------------------------------------------------------------
__global__ void mask_kernel(const float4* __restrict__ props,
                            const unsigned int* __restrict__ masks,
                            float* __restrict__ out)
{
    int b = blockIdx.y, i = blockIdx.x;
    int t = threadIdx.x;                  // 0..783
    float* dst = out + MASK_OFF + ((size_t)b*TRAIN_ROIS + i)*(MASK_H*MASK_W);

    if (i >= g_poscount[b]) { dst[t] = 0.0f; return; }

    int p = g_poslist[b*NUM_POS + i];
    float4 r = props[b*NP + p];
    int g = g_arg[b*NP + p];

    int y = t / MASK_W, x = t % MASK_W;

    float fy = xdiv((float)y, (float)(MASK_H-1));
    float fx = xdiv((float)x, (float)(MASK_W-1));
    float sy = __fadd_rn(__fmul_rn(r.x, 319.f),
                         __fmul_rn(__fmul_rn(fy, __fsub_rn(r.z,r.x)), 319.f));
    sy = fminf(fmaxf(sy, 0.f), 319.f);
    float sx = __fadd_rn(__fmul_rn(r.y, 319.f),
                         __fmul_rn(__fmul_rn(fx, __fsub_rn(r.w,r.y)), 319.f));
    sx = fminf(fmaxf(sx, 0.f), 319.f);

    int y0 = min(max((int)floorf(sy), 0), MH-2);
    int x0 = min(max((int)floorf(sx), 0), MW-2);
    float wy = __fsub_rn(sy, (float)y0);
    float wx = __fsub_rn(sx, (float)x0);

    size_t i00 = (((size_t)b*MH + y0)*MW + x0)*NG + g;
    float c00 = masks[i00]                    ? 1.f : 0.f;
    float c01 = masks[i00 + NG]               ? 1.f : 0.f;
    float c10 = masks[i00 + (size_t)MW*NG]    ? 1.f : 0.f;
    float c11 = masks[i00 + (size_t)MW*NG+NG] ? 1.f : 0.f;

    float top = __fadd_rn(__fmul_rn(c00, __fsub_rn(1.f,wx)), __fmul_rn(c01, wx));
    float bot = __fadd_rn(__fmul_rn(c10, __fsub_rn(1.f,wx)), __fmul_rn(c11, wx));
    float val = __fadd_rn(__fmul_rn(top, __fsub_rn(1.f,wy)), __fmul_rn(bot, wy));

    dst[t] = rintf(val);
}

// ---------------------------------------------------------------------------
extern "C" void kernel_launch(void* const* d_in, const int* in_sizes, int n_in,
                              void* d_out, int out_size)
{
    // Bind inputs by element count (all four are distinct) — immune to ordering.
    const float4*       props = 0;
    const int*          cls   = 0;
    const float4*       gts   = 0;
    const unsigned int* masks = 0;
    for (int i = 0; i < n_in; ++i) {
        switch (in_sizes[i]) {
            case BN*NP*4:              props = (const float4*)d_in[i];       break;
            case BN*NG:                cls   = (const int*)d_in[i];          break;
            case BN*NG*4:              gts   = (const float4*)d_in[i];       break;
            default:                   masks = (const unsigned int*)d_in[i]; break;
        }
    }
    float* out = (float*)d_out;

    fused_select<<<BN, 1024>>>(props, gts);
    slots_kernel<<<BN, 256>>>(props, gts, cls, out);
    mask_kernel<<<dim3(TRAIN_ROIS, BN), MASK_H*MASK_W>>>(props, masks, out);
}

// round 7
// speedup vs baseline: 4.1462x; 1.4599x over previous
#include <cuda_runtime.h>

#define BN 8
#define NP 2000
#define NG 100
#define MH 320
#define MW 320
#define NUM_POS 66
#define NUM_NEG 134
#define TRAIN_ROIS 200
#define MASK_H 28
#define MASK_W 28

// output layout (flattened tuple, float32)
#define ROIS_OFF  0
#define CLS_OFF   (BN*TRAIN_ROIS*4)            /* 6400 */
#define DELTA_OFF (CLS_OFF + BN*TRAIN_ROIS)    /* 8000 */
#define MASK_OFF  (DELTA_OFF + BN*TRAIN_ROIS*4)/* 14400 */

__device__ unsigned g_keyhi[BN*NP];   // ~orderable(maxiou): ascending = value desc
__device__ int      g_arg[BN*NP];
__device__ unsigned char g_valid[BN*NP];
__device__ int g_poslist[BN*NUM_POS];
__device__ int g_poscount[BN];

// XLA GPU compiles f32 divide with nvptx-prec-divf32=1 -> div.full.f32.
__device__ __forceinline__ float xdiv(float a, float b) {
    float r;
    asm("div.full.f32 %0, %1, %2;" : "=f"(r) : "f"(a), "f"(b));
    return r;
}

__device__ __forceinline__ unsigned orderable(float v) {
    unsigned u = __float_as_uint(v);
    return (u & 0x80000000u) ? ~u : (u | 0x80000000u);
}
// v >= 0.5 <=> hi = ~ord(v) <= ~ord(0.5) = 0x40FFFFFF
__device__ __forceinline__ int pos_hi(unsigned hi) { return hi <= 0x40FFFFFFu; }

// ---------------------------------------------------------------------------
// Kernel 1 (chip-wide): per-proposal max IoU + argmax (first-max = jnp.argmax)
// ---------------------------------------------------------------------------
__global__ void iou_kernel(const float4* __restrict__ props,
                           const float4* __restrict__ gts)
{
    int idx = blockIdx.x * blockDim.x + threadIdx.x;
    if (idx >= BN*NP) return;
    int b = idx / NP;
    float4 p = props[idx];
    unsigned char valid = (p.x!=0.f)||(p.y!=0.f)||(p.z!=0.f)||(p.w!=0.f);
    float area_a = __fmul_rn(__fsub_rn(p.z,p.x), __fsub_rn(p.w,p.y));
    float best = -2.0f; int bg = 0;
    #pragma unroll 4
    for (int g = 0; g < NG; ++g) {
        float4 q = gts[b*NG + g];
        int vg = (q.x!=0.f)||(q.y!=0.f)||(q.z!=0.f)||(q.w!=0.f);
        float y1 = fmaxf(p.x, q.x), x1 = fmaxf(p.y, q.y);
        float y2 = fminf(p.z, q.z), x2 = fminf(p.w, q.w);
        float inter = __fmul_rn(fmaxf(__fsub_rn(y2,y1),0.f),
                                fmaxf(__fsub_rn(x2,x1),0.f));
        float area_b = __fmul_rn(__fsub_rn(q.z,q.x), __fsub_rn(q.w,q.y));
        float uni = __fsub_rn(__fadd_rn(area_a, area_b), inter);
        float iou = xdiv(inter, fmaxf(uni, 1e-8f));
        float v = (vg && valid) ? iou : -1.0f;
        if (v > best) { best = v; bg = g; }
    }
    g_keyhi[idx] = ~orderable(best);
    g_arg[idx]   = bg;
    g_valid[idx] = valid;
}

// ---------------------------------------------------------------------------
// Kernel 2 (one block of 1024 per batch): sort + select + slots.
// Bitonic sort of 2048 keys (value desc, idx asc); strides j<=32 are
// warp-local (each warp owns a 64-aligned block), so only j>=64 phases and
// the first phase after them need __syncthreads. Filtered extraction via
// warp-shuffle scans. Tail computes rois/class/deltas for all 200 slots.
// ---------------------------------------------------------------------------
__global__ __launch_bounds__(1024) void select_kernel(const float4* __restrict__ props,
                                                      const float4* __restrict__ gts,
                                                      const int*    __restrict__ cls,
                                                      float* __restrict__ out)
{
    int b = blockIdx.x, t = threadIdx.x;
    int lane = t & 31, wid = t >> 5;
    __shared__ unsigned long long keys[2048];
    __shared__ unsigned char svalid[2048];
    __shared__ int warpsum[32];
    __shared__ int s_pos[NUM_POS];
    __shared__ int s_neg[NUM_NEG];
    __shared__ int s_cnt[4];   // totpos, totneg, pc, nc

    // load packed keys: (keyhi << 32) | idx ; padding sorts to end
    #pragma unroll
    for (int rep = 0; rep < 2; ++rep) {
        int i = t + rep*1024;
        unsigned long long k = ~0ull;
        unsigned char v = 0;
        if (i < NP) {
            k = (((unsigned long long)g_keyhi[b*NP + i]) << 32) | (unsigned)i;
            v = g_valid[b*NP + i];
        }
        keys[i] = k;
        svalid[i] = v;
    }

    // ---- bitonic sort ascending ----
    int prevj = 1 << 30;
    for (int kk = 2; kk <= 2048; kk <<= 1) {
        for (int j = kk >> 1; j > 0; j >>= 1) {
            if (j >= 64 || prevj >= 64) __syncthreads(); else __syncwarp();
            int i  = ((t & ~(j-1)) << 1) | (t & (j-1));
            int ix = i | j;
            bool up = ((i & kk) == 0);
            unsigned long long a = keys[i], c = keys[ix];
            if ((a > c) == up) { keys[i] = c; keys[ix] = a; }
            prevj = j;
        }
    }
    __syncthreads();

    // ---- filtered extraction (pass 0: pos, pass 1: neg) ----
    for (int pass = 0; pass < 2; ++pass) {
        unsigned long long k0 = keys[2*t], k1 = keys[2*t+1];
        unsigned hi0 = (unsigned)(k0 >> 32), hi1 = (unsigned)(k1 >> 32);
        unsigned id0 = (unsigned)(k0 & 0xFFFFFFFFu), id1 = (unsigned)(k1 & 0xFFFFFFFFu);
        int fa, fb;
        if (pass == 0) {
            fa = pos_hi(hi0);
            fb = pos_hi(hi1);
        } else {
            fa = (id0 < NP) && !pos_hi(hi0) && svalid[id0];
            fb = (id1 < NP) && !pos_hi(hi1) && svalid[id1];
        }
        int s = fa + fb;
        // warp inclusive scan
        int x = s;
        #pragma unroll
        for (int off = 1; off < 32; off <<= 1) {
            int y = __shfl_up_sync(0xFFFFFFFFu, x, off);
            if (lane >= off) x += y;
        }
        if (lane == 31) warpsum[wid] = x;
        __syncthreads();
        if (t < 32) {
            int v = warpsum[t];
            #pragma unroll
            for (int off = 1; off < 32; off <<= 1) {
                int y = __shfl_up_sync(0xFFFFFFFFu, v, off);
                if (t >= off) v += y;
            }
            warpsum[t] = v;
        }
        __syncthreads();
        int incl = x + (wid ? warpsum[wid-1] : 0);
        int excl = incl - s;
        if (pass == 0) {
            if (fa && excl < NUM_POS)        s_pos[excl]      = (int)id0;
            if (fb && (excl + fa) < NUM_POS) s_pos[excl + fa] = (int)id1;
        } else {
            if (fa && excl < NUM_NEG)        s_neg[excl]      = (int)id0;
            if (fb && (excl + fa) < NUM_NEG) s_neg[excl + fa] = (int)id1;
        }
        if (t == 0) s_cnt[pass] = 0;   // placeholder; total read below
        if (t == 31+0) {}              // (no-op)
        if (t == 0) s_cnt[pass] = warpsum[31];
        __syncthreads();
    }

    if (t == 0) {
        int pc = min(s_cnt[0], NUM_POS);
        int nc = (int)xdiv((float)pc, 0.33f) - pc;   // reference's div.full
        nc = min(nc, s_cnt[1]);
        nc = min(nc, NUM_NEG);
        if (nc < 0) nc = 0;
        s_cnt[2] = pc;
        s_cnt[3] = nc;
        g_poscount[b] = pc;
    }
    __syncthreads();
    int pc = s_cnt[2], nc = s_cnt[3];

    // publish poslist for the mask kernel
    if (t < NUM_POS && t < pc) g_poslist[b*NUM_POS + t] = s_pos[t];

    // ---- slots tail: rois / class / deltas for all 200 slots ----
    if (t < TRAIN_ROIS) {
        float4 roi = make_float4(0.f,0.f,0.f,0.f);
        float  c   = 0.f;
        float4 dd  = make_float4(0.f,0.f,0.f,0.f);

        if (t < NUM_POS) {
            if (t < pc) {
                int p = s_pos[t];
                float4 r = props[b*NP + p];
                roi = r;
                int g = g_arg[b*NP + p];
                c = (float)cls[b*NG + g];
                float4 q = gts[b*NG + g];
                float h  = fmaxf(__fsub_rn(r.z,r.x), 1e-8f);
                float w  = fmaxf(__fsub_rn(r.w,r.y), 1e-8f);
                float cy = __fadd_rn(r.x, __fmul_rn(0.5f,h));
                float cx = __fadd_rn(r.y, __fmul_rn(0.5f,w));
                float gh  = fmaxf(__fsub_rn(q.z,q.x), 1e-8f);
                float gw  = fmaxf(__fsub_rn(q.w,q.y), 1e-8f);
                float gcy = __fadd_rn(q.x, __fmul_rn(0.5f,gh));
                float gcx = __fadd_rn(q.y, __fmul_rn(0.5f,gw));
                dd.x = xdiv(xdiv(__fsub_rn(gcy,cy), h), 0.1f);
                dd.y = xdiv(xdiv(__fsub_rn(gcx,cx), w), 0.1f);
                dd.z = xdiv(logf(xdiv(gh,h)), 0.2f);
                dd.w = xdiv(logf(xdiv(gw,w)), 0.2f);
            }
        } else {
            int j = t - NUM_POS;
            if (j < nc) {
                int p = s_neg[j];
                roi = props[b*NP + p];
            }
        }

        ((float4*)(out + ROIS_OFF))[b*TRAIN_ROIS + t]  = roi;
        out[CLS_OFF + b*TRAIN_ROIS + t]                = c;
        ((float4*)(out + DELTA_OFF))[b*TRAIN_ROIS + t] = dd;
    }
}

// ---------------------------------------------------------------------------
// Kernel 3: masks for ALL 200 slots per batch (bilinear crop for selected
// positives, zeros elsewhere).
// ---------------------------------------------------------------------------
__global__ void mask_kernel(const float4* __restrict__ props,
                            const unsigned int* __restrict__ masks,
                            float* __restrict__ out)
{
    int b = blockIdx.y, i = blockIdx.x;
    int t = threadIdx.x;                  // 0..783
    float* dst = out + MASK_OFF + ((size_t)b*TRAIN_ROIS + i)*(MASK_H*MASK_W);

    if (i >= g_poscount[b]) { dst[t] = 0.0f; return; }

    int p = g_poslist[b*NUM_POS + i];
    float4 r = props[b*NP + p];
    int g = g_arg[b*NP + p];

    int y = t / MASK_W, x = t % MASK_W;

    float fy = xdiv((float)y, (float)(MASK_H-1));
    float fx = xdiv((float)x, (float)(MASK_W-1));
    float sy = __fadd_rn(__fmul_rn(r.x, 319.f),
                         __fmul_rn(__fmul_rn(fy, __fsub_rn(r.z,r.x)), 319.f));
    sy = fminf(fmaxf(sy, 0.f), 319.f);
    float sx = __fadd_rn(__fmul_rn(r.y, 319.f),
                         __fmul_rn(__fmul_rn(fx, __fsub_rn(r.w,r.y)), 319.f));
    sx = fminf(fmaxf(sx, 0.f), 319.f);

    int y0 = min(max((int)floorf(sy), 0), MH-2);
    int x0 = min(max((int)floorf(sx), 0), MW-2);
    float wy = __fsub_rn(sy, (float)y0);
    float wx = __fsub_rn(sx, (float)x0);

    size_t i00 = (((size_t)b*MH + y0)*MW + x0)*NG + g;
    float c00 = masks[i00]                    ? 1.f : 0.f;
    float c01 = masks[i00 + NG]               ? 1.f : 0.f;
    float c10 = masks[i00 + (size_t)MW*NG]    ? 1.f : 0.f;
    float c11 = masks[i00 + (size_t)MW*NG+NG] ? 1.f : 0.f;

    float top = __fadd_rn(__fmul_rn(c00, __fsub_rn(1.f,wx)), __fmul_rn(c01, wx));
    float bot = __fadd_rn(__fmul_rn(c10, __fsub_rn(1.f,wx)), __fmul_rn(c11, wx));
    float val = __fadd_rn(__fmul_rn(top, __fsub_rn(1.f,wy)), __fmul_rn(bot, wy));

    dst[t] = rintf(val);
}

// ---------------------------------------------------------------------------
extern "C" void kernel_launch(void* const* d_in, const int* in_sizes, int n_in,
                              void* d_out, int out_size)
{
    const float4*       props = 0;
    const int*          cls   = 0;
    const float4*       gts   = 0;
    const unsigned int* masks = 0;
    for (int i = 0; i < n_in; ++i) {
        switch (in_sizes[i]) {
            case BN*NP*4:              props = (const float4*)d_in[i];       break;
            case BN*NG:                cls   = (const int*)d_in[i];          break;
            case BN*NG*4:              gts   = (const float4*)d_in[i];       break;
            default:                   masks = (const unsigned int*)d_in[i]; break;
        }
    }
    float* out = (float*)d_out;

    iou_kernel<<<(BN*NP + 255)/256, 256>>>(props, gts);
    select_kernel<<<BN, 1024>>>(props, gts, cls, out);
    mask_kernel<<<dim3(TRAIN_ROIS, BN), MASK_H*MASK_W>>>(props, masks, out);
}

// round 8
// speedup vs baseline: 4.6353x; 1.1179x over previous
#include <cuda_runtime.h>

#define BN 8
#define NP 2000
#define NG 100
#define MH 320
#define MW 320
#define NUM_POS 66
#define NUM_NEG 134
#define TRAIN_ROIS 200
#define MASK_H 28
#define MASK_W 28

// output layout (flattened tuple, float32)
#define ROIS_OFF  0
#define CLS_OFF   (BN*TRAIN_ROIS*4)            /* 6400 */
#define DELTA_OFF (CLS_OFF + BN*TRAIN_ROIS)    /* 8000 */
#define MASK_OFF  (DELTA_OFF + BN*TRAIN_ROIS*4)/* 14400 */

__device__ unsigned g_keyhi[BN*NP];   // ~orderable(maxiou): ascending = value desc
__device__ int      g_arg[BN*NP];
__device__ unsigned char g_valid[BN*NP];
__device__ int g_poslist[BN*NUM_POS];
__device__ int g_poscount[BN];

// XLA GPU compiles f32 divide with nvptx-prec-divf32=1 -> div.full.f32.
__device__ __forceinline__ float xdiv(float a, float b) {
    float r;
    asm("div.full.f32 %0, %1, %2;" : "=f"(r) : "f"(a), "f"(b));
    return r;
}

__device__ __forceinline__ unsigned orderable(float v) {
    unsigned u = __float_as_uint(v);
    return (u & 0x80000000u) ? ~u : (u | 0x80000000u);
}
// v >= 0.5 <=> hi = ~ord(v) <= ~ord(0.5) = 0x40FFFFFF
__device__ __forceinline__ int pos_hi(unsigned hi) { return hi <= 0x40FFFFFFu; }

// ---------------------------------------------------------------------------
// Kernel 1: IoU max/argmax, 4 threads per proposal (25 GTs each) + shuffle
// max-reduce of packed (orderable(v)<<32)|(NG-1-g) keys. Max = highest value,
// tie -> lowest g: identical to the sequential first-max (jnp.argmax).
// ---------------------------------------------------------------------------
__global__ void iou_kernel(const float4* __restrict__ props,
                           const float4* __restrict__ gts)
{
    int gid = blockIdx.x * blockDim.x + threadIdx.x;
    int pid = gid >> 2;              // proposal index (global)
    int sub = gid & 3;               // which quarter of the GT list
    if (pid >= BN*NP) return;
    int b = pid / NP;

    float4 p = props[pid];
    unsigned char valid = (p.x!=0.f)||(p.y!=0.f)||(p.z!=0.f)||(p.w!=0.f);
    float area_a = __fmul_rn(__fsub_rn(p.z,p.x), __fsub_rn(p.w,p.y));

    unsigned long long bestk = 0ull;   // all candidate keys are > 0
    int g0 = sub * (NG/4);
    #pragma unroll 5
    for (int gg = 0; gg < NG/4; ++gg) {
        int g = g0 + gg;
        float4 q = gts[b*NG + g];
        int vg = (q.x!=0.f)||(q.y!=0.f)||(q.z!=0.f)||(q.w!=0.f);
        float y1 = fmaxf(p.x, q.x), x1 = fmaxf(p.y, q.y);
        float y2 = fminf(p.z, q.z), x2 = fminf(p.w, q.w);
        float inter = __fmul_rn(fmaxf(__fsub_rn(y2,y1),0.f),
                                fmaxf(__fsub_rn(x2,x1),0.f));
        float area_b = __fmul_rn(__fsub_rn(q.z,q.x), __fsub_rn(q.w,q.y));
        float uni = __fsub_rn(__fadd_rn(area_a, area_b), inter);
        float iou = xdiv(inter, fmaxf(uni, 1e-8f));
        float v = (vg && valid) ? iou : -1.0f;
        unsigned long long k = (((unsigned long long)orderable(v)) << 32)
                             | (unsigned)(NG - 1 - g);
        if (k > bestk) bestk = k;
    }

    // reduce across the 4 threads of this proposal (groups of 4 are lane-aligned)
    #pragma unroll
    for (int off = 1; off < 4; off <<= 1) {
        unsigned long long o = __shfl_xor_sync(0xFFFFFFFFu, bestk, off);
        if (o > bestk) bestk = o;
    }

    if (sub == 0) {
        unsigned ordv = (unsigned)(bestk >> 32);
        int bg = NG - 1 - (int)(bestk & 0xFFFFFFFFu);
        g_keyhi[pid] = ~ordv;
        g_arg[pid]   = bg;
        g_valid[pid] = valid;
    }
}

// ---------------------------------------------------------------------------
// Kernel 2 (one block of 1024 per batch): sort + select + slots.
// Bitonic sort of 2048 keys (value desc, idx asc); strides j<=32 are
// warp-local, so only phases touching j>=64 need __syncthreads. Filtered
// extraction via warp-shuffle scans. Tail computes rois/class/deltas.
// ---------------------------------------------------------------------------
__global__ __launch_bounds__(1024) void select_kernel(const float4* __restrict__ props,
                                                      const float4* __restrict__ gts,
                                                      const int*    __restrict__ cls,
                                                      float* __restrict__ out)
{
    int b = blockIdx.x, t = threadIdx.x;
    int lane = t & 31, wid = t >> 5;
    __shared__ unsigned long long keys[2048];
    __shared__ unsigned char svalid[2048];
    __shared__ int warpsum[32];
    __shared__ int s_pos[NUM_POS];
    __shared__ int s_neg[NUM_NEG];
    __shared__ int s_cnt[4];   // totpos, totneg, pc, nc

    // load packed keys: (keyhi << 32) | idx ; padding sorts to end
    #pragma unroll
    for (int rep = 0; rep < 2; ++rep) {
        int i = t + rep*1024;
        unsigned long long k = ~0ull;
        unsigned char v = 0;
        if (i < NP) {
            k = (((unsigned long long)g_keyhi[b*NP + i]) << 32) | (unsigned)i;
            v = g_valid[b*NP + i];
        }
        keys[i] = k;
        svalid[i] = v;
    }

    // ---- bitonic sort ascending ----
    int prevj = 1 << 30;
    for (int kk = 2; kk <= 2048; kk <<= 1) {
        for (int j = kk >> 1; j > 0; j >>= 1) {
            if (j >= 64 || prevj >= 64) __syncthreads(); else __syncwarp();
            int i  = ((t & ~(j-1)) << 1) | (t & (j-1));
            int ix = i | j;
            bool up = ((i & kk) == 0);
            unsigned long long a = keys[i], c = keys[ix];
            if ((a > c) == up) { keys[i] = c; keys[ix] = a; }
            prevj = j;
        }
    }
    __syncthreads();

    // ---- filtered extraction (pass 0: pos, pass 1: neg) ----
    for (int pass = 0; pass < 2; ++pass) {
        unsigned long long k0 = keys[2*t], k1 = keys[2*t+1];
        unsigned hi0 = (unsigned)(k0 >> 32), hi1 = (unsigned)(k1 >> 32);
        unsigned id0 = (unsigned)(k0 & 0xFFFFFFFFu), id1 = (unsigned)(k1 & 0xFFFFFFFFu);
        int fa, fb;
        if (pass == 0) {
            fa = pos_hi(hi0);
            fb = pos_hi(hi1);
        } else {
            fa = (id0 < NP) && !pos_hi(hi0) && svalid[id0];
            fb = (id1 < NP) && !pos_hi(hi1) && svalid[id1];
        }
        int s = fa + fb;
        int x = s;
        #pragma unroll
        for (int off = 1; off < 32; off <<= 1) {
            int y = __shfl_up_sync(0xFFFFFFFFu, x, off);
            if (lane >= off) x += y;
        }
        if (lane == 31) warpsum[wid] = x;
        __syncthreads();
        if (t < 32) {
            int v = warpsum[t];
            #pragma unroll
            for (int off = 1; off < 32; off <<= 1) {
                int y = __shfl_up_sync(0xFFFFFFFFu, v, off);
                if (t >= off) v += y;
            }
            warpsum[t] = v;
        }
        __syncthreads();
        int incl = x + (wid ? warpsum[wid-1] : 0);
        int excl = incl - s;
        if (pass == 0) {
            if (fa && excl < NUM_POS)        s_pos[excl]      = (int)id0;
            if (fb && (excl + fa) < NUM_POS) s_pos[excl + fa] = (int)id1;
        } else {
            if (fa && excl < NUM_NEG)        s_neg[excl]      = (int)id0;
            if (fb && (excl + fa) < NUM_NEG) s_neg[excl + fa] = (int)id1;
        }
        if (t == 0) s_cnt[pass] = warpsum[31];
        __syncthreads();
    }

    if (t == 0) {
        int pc = min(s_cnt[0], NUM_POS);
        int nc = (int)xdiv((float)pc, 0.33f) - pc;   // reference's div.full
        nc = min(nc, s_cnt[1]);
        nc = min(nc, NUM_NEG);
        if (nc < 0) nc = 0;
        s_cnt[2] = pc;
        s_cnt[3] = nc;
        g_poscount[b] = pc;
    }
    __syncthreads();
    int pc = s_cnt[2], nc = s_cnt[3];

    // publish poslist for the mask kernel
    if (t < NUM_POS && t < pc) g_poslist[b*NUM_POS + t] = s_pos[t];

    // ---- slots tail: rois / class / deltas for all 200 slots ----
    if (t < TRAIN_ROIS) {
        float4 roi = make_float4(0.f,0.f,0.f,0.f);
        float  c   = 0.f;
        float4 dd  = make_float4(0.f,0.f,0.f,0.f);

        if (t < NUM_POS) {
            if (t < pc) {
                int p = s_pos[t];
                float4 r = props[b*NP + p];
                roi = r;
                int g = g_arg[b*NP + p];
                c = (float)cls[b*NG + g];
                float4 q = gts[b*NG + g];
                float h  = fmaxf(__fsub_rn(r.z,r.x), 1e-8f);
                float w  = fmaxf(__fsub_rn(r.w,r.y), 1e-8f);
                float cy = __fadd_rn(r.x, __fmul_rn(0.5f,h));
                float cx = __fadd_rn(r.y, __fmul_rn(0.5f,w));
                float gh  = fmaxf(__fsub_rn(q.z,q.x), 1e-8f);
                float gw  = fmaxf(__fsub_rn(q.w,q.y), 1e-8f);
                float gcy = __fadd_rn(q.x, __fmul_rn(0.5f,gh));
                float gcx = __fadd_rn(q.y, __fmul_rn(0.5f,gw));
                dd.x = xdiv(xdiv(__fsub_rn(gcy,cy), h), 0.1f);
                dd.y = xdiv(xdiv(__fsub_rn(gcx,cx), w), 0.1f);
                dd.z = xdiv(logf(xdiv(gh,h)), 0.2f);
                dd.w = xdiv(logf(xdiv(gw,w)), 0.2f);
            }
        } else {
            int j = t - NUM_POS;
            if (j < nc) {
                int p = s_neg[j];
                roi = props[b*NP + p];
            }
        }

        ((float4*)(out + ROIS_OFF))[b*TRAIN_ROIS + t]  = roi;
        out[CLS_OFF + b*TRAIN_ROIS + t]                = c;
        ((float4*)(out + DELTA_OFF))[b*TRAIN_ROIS + t] = dd;
    }
}

// ---------------------------------------------------------------------------
// Kernel 3: masks for ALL 200 slots per batch (bilinear crop for selected
// positives, zeros elsewhere).
// ---------------------------------------------------------------------------
__global__ void mask_kernel(const float4* __restrict__ props,
                            const unsigned int* __restrict__ masks,
                            float* __restrict__ out)
{
    int b = blockIdx.y, i = blockIdx.x;
    int t = threadIdx.x;                  // 0..783
    float* dst = out + MASK_OFF + ((size_t)b*TRAIN_ROIS + i)*(MASK_H*MASK_W);

    if (i >= g_poscount[b]) { dst[t] = 0.0f; return; }

    int p = g_poslist[b*NUM_POS + i];
    float4 r = props[b*NP + p];
    int g = g_arg[b*NP + p];

    int y = t / MASK_W, x = t % MASK_W;

    float fy = xdiv((float)y, (float)(MASK_H-1));
    float fx = xdiv((float)x, (float)(MASK_W-1));
    float sy = __fadd_rn(__fmul_rn(r.x, 319.f),
                         __fmul_rn(__fmul_rn(fy, __fsub_rn(r.z,r.x)), 319.f));
    sy = fminf(fmaxf(sy, 0.f), 319.f);
    float sx = __fadd_rn(__fmul_rn(r.y, 319.f),
                         __fmul_rn(__fmul_rn(fx, __fsub_rn(r.w,r.y)), 319.f));
    sx = fminf(fmaxf(sx, 0.f), 319.f);

    int y0 = min(max((int)floorf(sy), 0), MH-2);
    int x0 = min(max((int)floorf(sx), 0), MW-2);
    float wy = __fsub_rn(sy, (float)y0);
    float wx = __fsub_rn(sx, (float)x0);

    size_t i00 = (((size_t)b*MH + y0)*MW + x0)*NG + g;
    float c00 = masks[i00]                    ? 1.f : 0.f;
    float c01 = masks[i00 + NG]               ? 1.f : 0.f;
    float c10 = masks[i00 + (size_t)MW*NG]    ? 1.f : 0.f;
    float c11 = masks[i00 + (size_t)MW*NG+NG] ? 1.f : 0.f;

    float top = __fadd_rn(__fmul_rn(c00, __fsub_rn(1.f,wx)), __fmul_rn(c01, wx));
    float bot = __fadd_rn(__fmul_rn(c10, __fsub_rn(1.f,wx)), __fmul_rn(c11, wx));
    float val = __fadd_rn(__fmul_rn(top, __fsub_rn(1.f,wy)), __fmul_rn(bot, wy));

    dst[t] = rintf(val);
}

// ---------------------------------------------------------------------------
extern "C" void kernel_launch(void* const* d_in, const int* in_sizes, int n_in,
                              void* d_out, int out_size)
{
    const float4*       props = 0;
    const int*          cls   = 0;
    const float4*       gts   = 0;
    const unsigned int* masks = 0;
    for (int i = 0; i < n_in; ++i) {
        switch (in_sizes[i]) {
            case BN*NP*4:              props = (const float4*)d_in[i];       break;
            case BN*NG:                cls   = (const int*)d_in[i];          break;
            case BN*NG*4:              gts   = (const float4*)d_in[i];       break;
            default:                   masks = (const unsigned int*)d_in[i]; break;
        }
    }
    float* out = (float*)d_out;

    iou_kernel<<<(BN*NP*4 + 255)/256, 256>>>(props, gts);
    select_kernel<<<BN, 1024>>>(props, gts, cls, out);
    mask_kernel<<<dim3(TRAIN_ROIS, BN), MASK_H*MASK_W>>>(props, masks, out);
}